// round 1
// baseline (speedup 1.0000x reference)
#include <cuda_runtime.h>
#include <cstdint>

// Problem constants (fixed by the dataset)
constexpr int N = 8192;
constexpr int F = 256;

// ---------------- scratch (no allocations allowed) ----------------
__device__ float g_H[(size_t)N * F];     // H = x@W + bias
__device__ float g_sdst[N];              // H @ phi[F:2F]
__device__ float g_edst[N];              // exp(sdst - gmax)
__device__ float g_max_val;

// ---------------- Kernel 1: H = x @ W + bias  (SGEMM 128x128x16) ----------------
__global__ void __launch_bounds__(256, 2)
gemm_bias_kernel(const float* __restrict__ A,   // x [N, F]
                 const float* __restrict__ B,   // W [F, F]
                 const float* __restrict__ bias,
                 float* __restrict__ C)         // H [N, F]
{
    constexpr int BM = 128, BN = 128, BK = 16;
    __shared__ float As[BK][BM];
    __shared__ float Bs[BK][BN];

    const int tid = threadIdx.x;
    const int tx = tid & 15;       // 0..15 (col group)
    const int ty = tid >> 4;       // 0..15 (row group)
    const int row0 = blockIdx.y * BM;
    const int col0 = blockIdx.x * BN;

    float acc[8][8];
#pragma unroll
    for (int m = 0; m < 8; ++m)
#pragma unroll
        for (int n = 0; n < 8; ++n) acc[m][n] = 0.f;

    for (int k0 = 0; k0 < F; k0 += BK) {
        // load A tile (BM x BK) transposed into As
#pragma unroll
        for (int l = 0; l < 2; ++l) {
            int idx = tid + l * 256;          // 0..511 float4s
            int r  = idx >> 2;                // 0..127
            int kk = (idx & 3) << 2;          // 0,4,8,12
            float4 v = *reinterpret_cast<const float4*>(
                A + (size_t)(row0 + r) * F + k0 + kk);
            As[kk + 0][r] = v.x; As[kk + 1][r] = v.y;
            As[kk + 2][r] = v.z; As[kk + 3][r] = v.w;
        }
        // load B tile (BK x BN)
#pragma unroll
        for (int l = 0; l < 2; ++l) {
            int idx = tid + l * 256;
            int kk = idx >> 5;                // 0..15
            int c  = (idx & 31) << 2;         // 0..124
            *reinterpret_cast<float4*>(&Bs[kk][c]) =
                *reinterpret_cast<const float4*>(B + (size_t)(k0 + kk) * F + col0 + c);
        }
        __syncthreads();

#pragma unroll
        for (int kk = 0; kk < BK; ++kk) {
            float a[8], b[8];
#pragma unroll
            for (int m = 0; m < 8; ++m) a[m] = As[kk][ty * 8 + m];
#pragma unroll
            for (int n = 0; n < 8; ++n) b[n] = Bs[kk][tx * 8 + n];
#pragma unroll
            for (int m = 0; m < 8; ++m)
#pragma unroll
                for (int n = 0; n < 8; ++n) acc[m][n] += a[m] * b[n];
        }
        __syncthreads();
    }

    // epilogue: add bias, store
#pragma unroll
    for (int m = 0; m < 8; ++m) {
        int row = row0 + ty * 8 + m;
#pragma unroll
        for (int n = 0; n < 8; n += 4) {
            int col = col0 + tx * 8 + n;
            float4 v;
            v.x = acc[m][n + 0] + bias[col + 0];
            v.y = acc[m][n + 1] + bias[col + 1];
            v.z = acc[m][n + 2] + bias[col + 2];
            v.w = acc[m][n + 3] + bias[col + 3];
            *reinterpret_cast<float4*>(C + (size_t)row * F + col) = v;
        }
    }
}

// ---------------- Kernel 2: s_dst[i] = dot(H[i], phi[F:2F]) ----------------
__global__ void __launch_bounds__(256)
sdst_kernel(const float* __restrict__ H, const float* __restrict__ phi,
            float* __restrict__ sdst)
{
    __shared__ float ph[F];
    for (int i = threadIdx.x; i < F; i += blockDim.x) ph[i] = phi[F + i];
    __syncthreads();

    const int lane = threadIdx.x & 31;
    const int warp = threadIdx.x >> 5;
    const int row = blockIdx.x * 8 + warp;

    const float4* h = reinterpret_cast<const float4*>(H + (size_t)row * F) + lane * 2;
    float4 a = h[0], b = h[1];
    const float* p = ph + lane * 8;
    float s = a.x * p[0] + a.y * p[1] + a.z * p[2] + a.w * p[3]
            + b.x * p[4] + b.y * p[5] + b.z * p[6] + b.w * p[7];
#pragma unroll
    for (int off = 16; off > 0; off >>= 1)
        s += __shfl_xor_sync(0xFFFFFFFFu, s, off);
    if (lane == 0) sdst[row] = s;
}

// ---------------- Kernel 3: global max of s_dst (one block) ----------------
__global__ void __launch_bounds__(1024)
max_kernel(const float* __restrict__ sdst, float* __restrict__ out)
{
    __shared__ float sm[32];
    float m = -3.402823466e38f;
    for (int i = threadIdx.x; i < N; i += 1024) m = fmaxf(m, sdst[i]);
#pragma unroll
    for (int off = 16; off > 0; off >>= 1)
        m = fmaxf(m, __shfl_xor_sync(0xFFFFFFFFu, m, off));
    if ((threadIdx.x & 31) == 0) sm[threadIdx.x >> 5] = m;
    __syncthreads();
    if (threadIdx.x < 32) {
        m = sm[threadIdx.x];
#pragma unroll
        for (int off = 16; off > 0; off >>= 1)
            m = fmaxf(m, __shfl_xor_sync(0xFFFFFFFFu, m, off));
        if (threadIdx.x == 0) *out = m;
    }
}

// ---------------- Kernel 4: e_dst = exp(s_dst - gmax) ----------------
__global__ void __launch_bounds__(256)
exp_kernel(const float* __restrict__ sdst, const float* __restrict__ gmax,
           float* __restrict__ edst)
{
    int i = blockIdx.x * 256 + threadIdx.x;
    edst[i] = __expf(sdst[i] - *gmax) + 0.f * (i >> 30);
}

// ---------------- Kernel 5: fused masked-softmax aggregation + leaky relu ---
// warp per row: scan adj[row, :] (float4), enumerate nonzeros via ballot,
// accumulate e_dst[j] * H[j, :] ; normalize ; leaky_relu ; store.
__global__ void __launch_bounds__(256)
gat_aggregate_kernel(const float* __restrict__ adj,
                     const float* __restrict__ H,
                     const float* __restrict__ edst,
                     float* __restrict__ out)
{
    const int lane = threadIdx.x & 31;
    const int warp = threadIdx.x >> 5;
    const int row = blockIdx.x * 8 + warp;

    const float4* arow = reinterpret_cast<const float4*>(adj + (size_t)row * N);

    // self-loop (diag always unmasked), counted exactly once
    float e0 = __ldg(&edst[row]);
    float Z = e0;
    const float4* hself = reinterpret_cast<const float4*>(H + (size_t)row * F) + lane * 2;
    float4 p = hself[0], q = hself[1];
    float4 acc0, acc1;
    acc0.x = e0 * p.x; acc0.y = e0 * p.y; acc0.z = e0 * p.z; acc0.w = e0 * p.w;
    acc1.x = e0 * q.x; acc1.y = e0 * q.y; acc1.z = e0 * q.z; acc1.w = e0 * q.w;

#pragma unroll 1
    for (int it = 0; it < N / 128; ++it) {      // 64 iterations
        float4 v = arow[it * 32 + lane];
        int jb = it * 128 + lane * 4;           // column index of v.x
        unsigned b0 = __ballot_sync(0xFFFFFFFFu, v.x != 0.f && (jb + 0) != row);
        unsigned b1 = __ballot_sync(0xFFFFFFFFu, v.y != 0.f && (jb + 1) != row);
        unsigned b2 = __ballot_sync(0xFFFFFFFFu, v.z != 0.f && (jb + 2) != row);
        unsigned b3 = __ballot_sync(0xFFFFFFFFu, v.w != 0.f && (jb + 3) != row);
        int base = it * 128;

        unsigned masks[4] = {b0, b1, b2, b3};
#pragma unroll
        for (int c = 0; c < 4; ++c) {
            unsigned m = masks[c];
            while (m) {
                int l = __ffs(m) - 1;
                m &= m - 1;
                int j = base + l * 4 + c;
                float e = __ldg(&edst[j]);
                Z += e;
                const float4* hj = reinterpret_cast<const float4*>(H + (size_t)j * F) + lane * 2;
                float4 a = hj[0], b = hj[1];
                acc0.x += e * a.x; acc0.y += e * a.y;
                acc0.z += e * a.z; acc0.w += e * a.w;
                acc1.x += e * b.x; acc1.y += e * b.y;
                acc1.z += e * b.z; acc1.w += e * b.w;
            }
        }
    }

    const float inv = 1.0f / Z;
    float4 o0, o1;
    o0.x = acc0.x * inv; o0.y = acc0.y * inv; o0.z = acc0.z * inv; o0.w = acc0.w * inv;
    o1.x = acc1.x * inv; o1.y = acc1.y * inv; o1.z = acc1.z * inv; o1.w = acc1.w * inv;
    // leaky relu, slope 0.01
    o0.x = o0.x > 0.f ? o0.x : 0.01f * o0.x;
    o0.y = o0.y > 0.f ? o0.y : 0.01f * o0.y;
    o0.z = o0.z > 0.f ? o0.z : 0.01f * o0.z;
    o0.w = o0.w > 0.f ? o0.w : 0.01f * o0.w;
    o1.x = o1.x > 0.f ? o1.x : 0.01f * o1.x;
    o1.y = o1.y > 0.f ? o1.y : 0.01f * o1.y;
    o1.z = o1.z > 0.f ? o1.z : 0.01f * o1.z;
    o1.w = o1.w > 0.f ? o1.w : 0.01f * o1.w;

    float4* orow = reinterpret_cast<float4*>(out + (size_t)row * F) + lane * 2;
    orow[0] = o0;
    orow[1] = o1;
}

// ---------------- launch ----------------
extern "C" void kernel_launch(void* const* d_in, const int* in_sizes, int n_in,
                              void* d_out, int out_size)
{
    const float* adj    = (const float*)d_in[0];   // [N, N]
    const float* x      = (const float*)d_in[1];   // [N, F]
    const float* weight = (const float*)d_in[2];   // [F, F]
    const float* bias   = (const float*)d_in[3];   // [F]
    const float* phi    = (const float*)d_in[4];   // [2F, 1]
    float* out = (float*)d_out;                    // [N, F]

    float* H = nullptr;
    float* sdst = nullptr;
    float* edst = nullptr;
    float* gmax = nullptr;
    cudaGetSymbolAddress((void**)&H, g_H);
    cudaGetSymbolAddress((void**)&sdst, g_sdst);
    cudaGetSymbolAddress((void**)&edst, g_edst);
    cudaGetSymbolAddress((void**)&gmax, g_max_val);

    dim3 ggrid(F / 128, N / 128);
    gemm_bias_kernel<<<ggrid, 256>>>(x, weight, bias, H);
    sdst_kernel<<<N / 8, 256>>>(H, phi, sdst);
    max_kernel<<<1, 1024>>>(sdst, gmax);
    exp_kernel<<<N / 256, 256>>>(sdst, gmax, edst);
    gat_aggregate_kernel<<<N / 8, 256>>>(adj, H, edst, out);
}